// round 8
// baseline (speedup 1.0000x reference)
#include <cuda_runtime.h>
#include <cuda_fp16.h>
#include <math.h>
#include <stdint.h>

// Problem constants (fixed shapes)
#define NN   4096      // N = V*B
#define BB   2048      // batch
#define VV   2         // views
#define DD   256       // feature dim
#define CC   1000      // classes
#define TEMP 0.07f
#define NTILE 32       // 4096 / 128
#define NBLK  (NTILE * (NTILE + 1) / 2)   // 528 triangular blocks

// Scratch (no cudaMalloc allowed)
__device__ __half g_f16[NN * DD];         // fp16 normalized features, view-major
__device__ float g_mod[BB];               // focal modulation per sample
__device__ float g_S[NN];                 // sum exp(l - M) over j != i
__device__ float g_P[NN];                 // sum over positives of (l - M)
__device__ float g_cnt[NN];               // positive counts
__device__ unsigned g_done;               // main-kernel completion counter

// ============================================================================
// PTX helpers (valid on compute_103 base target)
// ============================================================================
__device__ __forceinline__ uint32_t smem_to_u32(const void* p) {
    uint32_t a;
    asm("{ .reg .u64 t; cvta.to.shared.u64 t, %1; cvt.u32.u64 %0, t; }"
        : "=r"(a) : "l"(p));
    return a;
}
#define SMEM_SWIZZLE_128B(byte_offset) \
    ((byte_offset) ^ (((byte_offset) >> 3) & 0x70))

// mma.sync fp16 (sm_70+): D(16x8 f32) += A(16x16 f16) * B(16x8 f16)
#define MMA_F16(d, a, b0, b1) \
    asm volatile("mma.sync.aligned.m16n8k16.row.col.f32.f16.f16.f32 " \
        "{%0,%1,%2,%3}, {%4,%5,%6,%7}, {%8,%9}, {%0,%1,%2,%3};" \
        : "+f"((d)[0]), "+f"((d)[1]), "+f"((d)[2]), "+f"((d)[3]) \
        : "r"((a)[0]), "r"((a)[1]), "r"((a)[2]), "r"((a)[3]), \
          "r"(b0), "r"(b1))

#define LDSM_X4(r0, r1, r2, r3, addr) \
    asm volatile("ldmatrix.sync.aligned.m8n8.x4.shared.b16 {%0,%1,%2,%3}, [%4];" \
        : "=r"(r0), "=r"(r1), "=r"(r2), "=r"(r3) : "r"(addr))

#define CP_ASYNC_16(dst, src) \
    asm volatile("cp.async.cg.shared.global [%0], [%1], 16;" \
        :: "r"(dst), "l"(src) : "memory")
#define CP_ASYNC_COMMIT() asm volatile("cp.async.commit_group;" ::: "memory")
#define CP_ASYNC_WAIT(n)  asm volatile("cp.async.wait_group %0;" :: "n"(n) : "memory")

// ---------------------------------------------------------------------------
// K0 (prep): blocks [0,512): normalize+restack -> fp16, zero accumulators.
//            blocks [512,2560): focal modulation per sample (256 threads).
// ---------------------------------------------------------------------------
__global__ void __launch_bounds__(256) prep_kernel(
    const float* __restrict__ feats, const float* __restrict__ preds,
    const int* __restrict__ labels)
{
    const int tid = threadIdx.x, lane = tid & 31, w = tid >> 5;

    if (blockIdx.x < 512) {
        // ---- norm: one warp per output row ----
        int gw = blockIdx.x * 8 + w;
        int b = gw & (BB - 1);
        int v = gw >> 11;

        const float4* src = reinterpret_cast<const float4*>(feats + (size_t)(b * VV + v) * DD);
        float4 x0 = src[lane];
        float4 x1 = src[lane + 32];

        float ss = x0.x*x0.x + x0.y*x0.y + x0.z*x0.z + x0.w*x0.w
                 + x1.x*x1.x + x1.y*x1.y + x1.z*x1.z + x1.w*x1.w;
#pragma unroll
        for (int o = 16; o > 0; o >>= 1) ss += __shfl_xor_sync(0xffffffffu, ss, o);
        float inv = rsqrtf(ss);

        __half2 h0 = __floats2half2_rn(x0.x * inv, x0.y * inv);
        __half2 h1 = __floats2half2_rn(x0.z * inv, x0.w * inv);
        __half2 h2 = __floats2half2_rn(x1.x * inv, x1.y * inv);
        __half2 h3 = __floats2half2_rn(x1.z * inv, x1.w * inv);

        __half2* hp = reinterpret_cast<__half2*>(g_f16 + (size_t)gw * DD);
        hp[2 * lane]          = h0;
        hp[2 * lane + 1]      = h1;
        hp[64 + 2 * lane]     = h2;
        hp[64 + 2 * lane + 1] = h3;

        if (lane == 0) { g_S[gw] = 0.f; g_P[gw] = 0.f; g_cnt[gw] = 0.f; }
    } else {
        // ---- mod: one block per sample ----
        __shared__ float sh8[8];
        int b = blockIdx.x - 512;
        const float* row = preds + (size_t)b * CC;

        float mx = -1e30f;
        for (int c = tid; c < CC; c += 256) mx = fmaxf(mx, row[c]);
#pragma unroll
        for (int o = 16; o > 0; o >>= 1) mx = fmaxf(mx, __shfl_xor_sync(0xffffffffu, mx, o));
        if (lane == 0) sh8[w] = mx;
        __syncthreads();
        mx = sh8[0];
#pragma unroll
        for (int q = 1; q < 8; ++q) mx = fmaxf(mx, sh8[q]);
        __syncthreads();

        float s = 0.f;
        for (int c = tid; c < CC; c += 256) s += __expf(row[c] - mx);
#pragma unroll
        for (int o = 16; o > 0; o >>= 1) s += __shfl_xor_sync(0xffffffffu, s, o);
        if (lane == 0) sh8[w] = s;
        __syncthreads();

        if (tid == 0) {
            float ssum = 0.f;
#pragma unroll
            for (int q = 0; q < 8; ++q) ssum += sh8[q];
            float nll = row[labels[b]] - mx - logf(ssum);
            float pt  = __expf(nll);
            float om  = 1.f - pt;
            g_mod[b]  = om * om;
        }
    }
}

// ---------------------------------------------------------------------------
// K1 (main): symmetric fp16 HMMA Gram GEMM over triangular 128x128 tiles.
// 512 threads / 16 warps per CTA, warp tile 32x32 (acc = 32 regs) so two
// CTAs/SM give 32 resident warps for latency hiding.
// Off-diagonal tiles scatter each element to row i AND row j (col reduce).
// Last finishing block performs the final loss reduction (fused finalize).
// ---------------------------------------------------------------------------
#define OFF_A 0
#define OFF_B 16384
#define STAGE_BYTES 32768
#define DYN_SMEM (2 * STAGE_BYTES + 1024)
#define MTHREADS 512

__device__ __forceinline__ void load_tile_async(uint32_t dstb, const __half* src,
                                                int row0, int kc, int tid) {
    // 128 rows x 64 halfs (128 B) per tile = 1024 16B segments
#pragma unroll
    for (int it = 0; it < 2; ++it) {
        int seg = tid + it * MTHREADS;
        int r = seg >> 3, sc = seg & 7;
        const void* g = src + (size_t)(row0 + r) * DD + kc * 64 + sc * 8;
        uint32_t off = (uint32_t)(r * 128 + sc * 16);
        CP_ASYNC_16(dstb + SMEM_SWIZZLE_128B(off), g);
    }
}

__global__ void __launch_bounds__(MTHREADS, 2) main_kernel(const int* __restrict__ labels,
                                                           float* __restrict__ out) {
    extern __shared__ char dsm[];
    __shared__ int   rlab[128], clab[128];
    __shared__ float sSr[128], sPr[128], sCr[128];
    __shared__ float sSc[128], sPc[128], sCc[128];
    __shared__ float red[MTHREADS];
    __shared__ unsigned isLast;

    const int tid  = threadIdx.x;
    const int w    = tid >> 5;
    const int lane = tid & 31;

    // triangular decode: block -> (bi, bj), bi <= bj
    int bi = 0, rem = blockIdx.x;
    while (rem >= NTILE - bi) { rem -= NTILE - bi; ++bi; }
    const int bj = bi + rem;
    const int i0 = bi * 128, j0 = bj * 128;
    const bool diag = (bi == bj);

    uint32_t dsm_u = smem_to_u32(dsm);
    uint32_t sb    = (dsm_u + 1023u) & ~1023u;

    if (tid < 128) {
        sSr[tid] = 0.f; sPr[tid] = 0.f; sCr[tid] = 0.f;
        sSc[tid] = 0.f; sPc[tid] = 0.f; sCc[tid] = 0.f;
        rlab[tid] = labels[(i0 + tid) & (BB - 1)];
        clab[tid] = labels[(j0 + tid) & (BB - 1)];
    }

    const float invT = 1.0f / TEMP;
    const int wm = w >> 2;          // 0..3 -> rows wm*32..+31
    const int wn = w & 3;           // 0..3 -> cols wn*32..+31
    __syncthreads();

    float acc[2][4][4];
#pragma unroll
    for (int mf = 0; mf < 2; ++mf)
#pragma unroll
        for (int nf = 0; nf < 4; ++nf)
#pragma unroll
            for (int q = 0; q < 4; ++q) acc[mf][nf][q] = 0.f;

    // prologue: chunk 0 -> buf 0
    load_tile_async(sb + OFF_A, g_f16, i0, 0, tid);
    load_tile_async(sb + OFF_B, g_f16, j0, 0, tid);
    CP_ASYNC_COMMIT();

    for (int kc = 0; kc < 4; ++kc) {
        if (kc < 3) {
            uint32_t stb = sb + ((kc + 1) & 1) * STAGE_BYTES;
            load_tile_async(stb + OFF_A, g_f16, i0, kc + 1, tid);
            load_tile_async(stb + OFF_B, g_f16, j0, kc + 1, tid);
            CP_ASYNC_COMMIT();
            CP_ASYNC_WAIT(1);
        } else {
            CP_ASYNC_WAIT(0);
        }
        __syncthreads();

        const uint32_t stb = sb + (kc & 1) * STAGE_BYTES;
#pragma unroll
        for (int ks = 0; ks < 4; ++ks) {
            uint32_t ah[2][4];
#pragma unroll
            for (int mf = 0; mf < 2; ++mf) {
                int row  = wm * 32 + mf * 16 + (lane & 15);
                int koff = ks * 16 + ((lane >> 4) << 3);
                uint32_t byoff = SMEM_SWIZZLE_128B((uint32_t)(row * 128 + koff * 2));
                LDSM_X4(ah[mf][0], ah[mf][1], ah[mf][2], ah[mf][3], stb + OFF_A + byoff);
            }
#pragma unroll
            for (int nf2 = 0; nf2 < 2; ++nf2) {
                int brow = wn * 32 + nf2 * 16 + (lane & 7) + ((lane >> 4) << 3);
                int bk   = ks * 16 + (((lane >> 3) & 1) << 3);
                uint32_t boff = SMEM_SWIZZLE_128B((uint32_t)(brow * 128 + bk * 2));
                uint32_t bh[4];
                LDSM_X4(bh[0], bh[1], bh[2], bh[3], stb + OFF_B + boff);
#pragma unroll
                for (int mf = 0; mf < 2; ++mf) {
                    MMA_F16(acc[mf][2*nf2],   ah[mf], bh[0], bh[1]);
                    MMA_F16(acc[mf][2*nf2+1], ah[mf], bh[2], bh[3]);
                }
            }
        }
        __syncthreads();
    }

    // ---------------- Epilogue ----------------
    // Fragment: lane holds rows (g, g+8) of each 16-row mf frag, cols 2t,2t+1.
    {
        const int g  = lane >> 2;
        const int t2 = (lane & 3) * 2;
        float rs[2][2], rp[2][2], rc[2][2];
#pragma unroll
        for (int mf = 0; mf < 2; ++mf)
#pragma unroll
            for (int h = 0; h < 2; ++h) { rs[mf][h] = 0.f; rp[mf][h] = 0.f; rc[mf][h] = 0.f; }

#pragma unroll
        for (int nf = 0; nf < 4; ++nf) {
            const int cb = wn * 32 + nf * 8 + t2;   // local cols cb, cb+1
            float cs[2] = {0.f, 0.f}, cp[2] = {0.f, 0.f}, cc[2] = {0.f, 0.f};
#pragma unroll
            for (int mf = 0; mf < 2; ++mf) {
                const int r0 = wm * 32 + mf * 16 + g;
                const int iA[2] = { i0 + r0, i0 + r0 + 8 };
                const int lA[2] = { rlab[r0], rlab[r0 + 8] };
#pragma unroll
                for (int h = 0; h < 2; ++h) {
#pragma unroll
                    for (int q = 0; q < 2; ++q) {
                        const int jloc = cb + q;
                        float l = fmaf(acc[mf][nf][h * 2 + q], invT, -invT);
                        bool excl = diag && (iA[h] == j0 + jloc);
                        float e  = excl ? 0.f : __expf(l);
                        float mm = (!excl && lA[h] == clab[jloc]) ? 1.f : 0.f;
                        rs[mf][h] += e;      rp[mf][h] += mm * l; rc[mf][h] += mm;
                        cs[q]     += e;      cp[q]     += mm * l; cc[q]     += mm;
                    }
                }
            }
            if (!diag) {
                // reduce column partials across the g axis (lanes xor 4,8,16)
#pragma unroll
                for (int o = 4; o <= 16; o <<= 1) {
#pragma unroll
                    for (int q = 0; q < 2; ++q) {
                        cs[q] += __shfl_xor_sync(0xffffffffu, cs[q], o);
                        cp[q] += __shfl_xor_sync(0xffffffffu, cp[q], o);
                        cc[q] += __shfl_xor_sync(0xffffffffu, cc[q], o);
                    }
                }
                if (g == 0) {
#pragma unroll
                    for (int q = 0; q < 2; ++q) {
                        atomicAdd(&sSc[cb + q], cs[q]);
                        atomicAdd(&sPc[cb + q], cp[q]);
                        atomicAdd(&sCc[cb + q], cc[q]);
                    }
                }
            }
        }
        // reduce row partials across the t axis (lanes xor 1,2)
#pragma unroll
        for (int mf = 0; mf < 2; ++mf) {
            const int r0 = wm * 32 + mf * 16 + g;
#pragma unroll
            for (int h = 0; h < 2; ++h) {
#pragma unroll
                for (int o = 1; o <= 2; o <<= 1) {
                    rs[mf][h] += __shfl_xor_sync(0xffffffffu, rs[mf][h], o);
                    rp[mf][h] += __shfl_xor_sync(0xffffffffu, rp[mf][h], o);
                    rc[mf][h] += __shfl_xor_sync(0xffffffffu, rc[mf][h], o);
                }
            }
            if ((lane & 3) == 0) {
                atomicAdd(&sSr[r0], rs[mf][0]);     atomicAdd(&sSr[r0 + 8], rs[mf][1]);
                atomicAdd(&sPr[r0], rp[mf][0]);     atomicAdd(&sPr[r0 + 8], rp[mf][1]);
                atomicAdd(&sCr[r0], rc[mf][0]);     atomicAdd(&sCr[r0 + 8], rc[mf][1]);
            }
        }
    }
    __syncthreads();
    if (tid < 128) {
        atomicAdd(&g_S[i0 + tid],   sSr[tid]);
        atomicAdd(&g_P[i0 + tid],   sPr[tid]);
        atomicAdd(&g_cnt[i0 + tid], sCr[tid]);
        if (!diag) {
            atomicAdd(&g_S[j0 + tid],   sSc[tid]);
            atomicAdd(&g_P[j0 + tid],   sPc[tid]);
            atomicAdd(&g_cnt[j0 + tid], sCc[tid]);
        }
    }

    // ---------------- Fused finalize (last block) ----------------
    __threadfence();
    __syncthreads();
    if (tid == 0) isLast = (atomicAdd(&g_done, 1u) == NBLK - 1) ? 1u : 0u;
    __syncthreads();
    if (isLast) {
        __threadfence();
        float accv = 0.f;
        for (int i = tid; i < NN; i += MTHREADS) {
            float Sv = __ldcg(&g_S[i]);
            float Pv = __ldcg(&g_P[i]);
            float Cv = __ldcg(&g_cnt[i]);
            float mv = __ldcg(&g_mod[i & (BB - 1)]);
            accv += mv * (Pv / Cv - logf(Sv));
        }
        red[tid] = accv;
        __syncthreads();
#pragma unroll
        for (int s = MTHREADS / 2; s > 0; s >>= 1) {
            if (tid < s) red[tid] += red[tid + s];
            __syncthreads();
        }
        if (tid == 0) { out[0] = -red[0] / (float)NN; g_done = 0u; }
    }
}

// ---------------------------------------------------------------------------
extern "C" void kernel_launch(void* const* d_in, const int* in_sizes, int n_in,
                              void* d_out, int out_size) {
    const float* feats  = (const float*)d_in[0];   // [B, V, D]
    const float* preds  = (const float*)d_in[1];   // [B, C]
    const int*   labels = (const int*)d_in[2];     // [B]
    float* out = (float*)d_out;

    cudaFuncSetAttribute(main_kernel, cudaFuncAttributeMaxDynamicSharedMemorySize, DYN_SMEM);

    prep_kernel<<<512 + BB, 256>>>(feats, preds, labels);
    main_kernel<<<NBLK, MTHREADS, DYN_SMEM>>>(labels, out);
}